// round 3
// baseline (speedup 1.0000x reference)
#include <cuda_runtime.h>
#include <cstdint>

#define Bsz 256
#define Tlen 512
#define HH 100
#define G4 400
#define Oout 3

typedef unsigned long long ull;

// Packed fp32x2 FMA (Blackwell FFMA2) + pack/unpack helpers
#define FMA2(d, a, b, c) asm("fma.rn.f32x2 %0, %1, %2, %3;" : "=l"(d) : "l"(a), "l"(b), "l"(c))
#define PACK2(d, lo, hi) asm("mov.b64 %0, {%1, %2};" : "=l"(d) : "f"(lo), "f"(hi))
#define UNPACK2(lo, hi, v) asm("mov.b64 {%0, %1}, %2;" : "=f"(lo), "=f"(hi) : "l"(v))

// ---------------------------------------------------------------------------
// Device globals (allocation-free scratch)
// ---------------------------------------------------------------------------
__device__ float g_h[(size_t)4 * Bsz * Tlen * HH];   // layer 0..3 hidden sequences (~210MB)
__device__ float g_hLast[Bsz * HH];                  // layer 4, t = T-1
__device__ volatile unsigned g_flag[4][32];          // producer progress (monotonic across replays)
__device__ unsigned g_epoch[160];                    // per-block launch counter (monotonic)

// ---------------------------------------------------------------------------
// Fast activations
// ---------------------------------------------------------------------------
__device__ __forceinline__ float sigf(float x) {
    return __fdividef(1.0f, 1.0f + __expf(-x));
}
__device__ __forceinline__ float tanh_(float x) {
    return __fdividef(2.0f, 1.0f + __expf(-2.0f * x)) - 1.0f;
}

// ---------------------------------------------------------------------------
// Dynamic smem layout (floats)
// ---------------------------------------------------------------------------
#define SM_WIH   0            // 40000 : W_ih [400][100] (layers 1-4)
#define SM_HPREV 40000        // 800   : staged h_{l-1}[t] (or x stage for layer 0)
#define SM_HOWN  40800        // 1600  : h_l[t-1] (max 16 rows)
#define SM_GSH   42400        // 6400  : gate pre-activations (max 16 rows x 400)
#define SM_TOTF  48800
#define SMEM_BYTES (SM_TOTF * 4)

// ---------------------------------------------------------------------------
// Persistent wavefront kernel: all 5 layers concurrently.
//   blocks 0..15   : layer 0, 16 batch rows each
//   blocks 16..143 : layers 1..4, 32 blocks/layer, 8 batch rows each
// Per step: phase A = W_hh (regs) x h_own(smem); phase B = W_ih (smem) x
// h_prev(staged from producer via global); activation; publish.
// Sync: producer does STG h[t], fence (next step), barrier, flag store;
// consumer spins on flag (addresses are first-touch, so no stale-L1 hazard).
// ---------------------------------------------------------------------------
__global__ __launch_bounds__(416, 1)
void lstm_wave(const float* __restrict__ x,      // [256,512,5]
               const float* __restrict__ W_ih0,  // [400,5]
               const float* __restrict__ W_hh0,  // [400,100]
               const float* __restrict__ b0,     // [400]
               const float* __restrict__ W_ih,   // [4,400,100]
               const float* __restrict__ W_hh,   // [4,400,100]
               const float* __restrict__ bb)     // [4,400]
{
    extern __shared__ float sm[];
    float* Wihs  = sm + SM_WIH;
    float* hprev = sm + SM_HPREV;
    float* hown  = sm + SM_HOWN;
    float* gsh   = sm + SM_GSH;
    __shared__ unsigned s_base;

    const int tid = threadIdx.x;
    const int bid = blockIdx.x;

    int layer, pb, row0, nr;
    if (bid < 16) { layer = 0; pb = bid;            row0 = bid * 16;  nr = 16; }
    else          { layer = 1 + (bid - 16) / 32; pb = (bid - 16) % 32; row0 = pb * 8; nr = 8; }

    if (tid == 0) {
        unsigned e = g_epoch[bid] + 1u;
        g_epoch[bid] = e;
        s_base = (e - 1u) * (unsigned)Tlen;
    }

    // W_hh row -> registers (k-pair packed)
    ull w2[50];
    float bg = 0.f;
    float w0[5] = {0, 0, 0, 0, 0};
    const float* whh_l = (layer == 0) ? W_hh0 : (W_hh + (size_t)(layer - 1) * G4 * HH);
    if (tid < G4) {
        const float4* wr = (const float4*)(whh_l + (size_t)tid * HH);
#pragma unroll
        for (int j = 0; j < 25; j++) {
            float4 v = wr[j];
            PACK2(w2[2 * j],     v.x, v.y);
            PACK2(w2[2 * j + 1], v.z, v.w);
        }
        bg = (layer == 0) ? b0[tid] : bb[(size_t)(layer - 1) * G4 + tid];
        if (layer == 0) {
#pragma unroll
            for (int k = 0; k < 5; k++) w0[k] = W_ih0[tid * 5 + k];
        }
    }
    // W_ih -> smem (layers 1..4)
    if (layer > 0) {
        const float4* Wg = (const float4*)(W_ih + (size_t)(layer - 1) * G4 * HH);
        float4* Ws4 = (float4*)Wihs;
        for (int i = tid; i < G4 * HH / 4; i += 416) Ws4[i] = Wg[i];
    }
    for (int i = tid; i < nr * HH; i += 416) hown[i] = 0.f;
    float c[4] = {0, 0, 0, 0};
    __syncthreads();
    const unsigned base = s_base;
    const int np = nr / 2;
    const int psrc = (layer == 1) ? (pb >> 1) : pb;

    for (int t = 0; t < Tlen; t++) {
        // Wait for producer to have published h_{l-1}[t]
        if (tid == 0 && layer > 0) {
            unsigned target = base + (unsigned)t + 1u;
            while ((int)(g_flag[layer - 1][psrc] - target) < 0) {}
        }
        __syncthreads();                       // S1
        __threadfence();                       // release for last step's STGs (drained: cheap)

        // Issue input-stage loads (in flight across phase A)
        float4 v4 = make_float4(0, 0, 0, 0);
        float xv = 0.f;
        if (layer > 0) {
            if (tid < nr * 25) {
                int r = tid / 25, p4 = tid - r * 25;
                const float* src = g_h + ((((size_t)(layer - 1) * Bsz + row0 + r) * Tlen + t) * HH);
                v4 = *(const float4*)(src + p4 * 4);
            }
        } else {
            if (tid < nr * 5) {
                int r = tid / 5, k = tid - r * 5;
                xv = x[((size_t)(row0 + r) * Tlen + t) * 5 + k];
            }
        }

        // Phase A: recurrent dot, row pairs
        if (tid < G4) {
            for (int p = 0; p < np; p++) {
                const ulonglong2* hA = (const ulonglong2*)&hown[(2 * p) * HH];
                const ulonglong2* hB = (const ulonglong2*)&hown[(2 * p + 1) * HH];
                ull a0, a1, e0, e1;
                PACK2(a0, bg, 0.f); PACK2(a1, 0.f, 0.f);
                PACK2(e0, bg, 0.f); PACK2(e1, 0.f, 0.f);
#pragma unroll
                for (int j = 0; j < 25; j++) {
                    ulonglong2 pA = hA[j], pB = hB[j];
                    FMA2(a0, w2[2 * j],     pA.x, a0);
                    FMA2(a1, w2[2 * j + 1], pA.y, a1);
                    FMA2(e0, w2[2 * j],     pB.x, e0);
                    FMA2(e1, w2[2 * j + 1], pB.y, e1);
                }
                float q0, q1, q2, q3;
                UNPACK2(q0, q1, a0); UNPACK2(q2, q3, a1);
                gsh[(2 * p) * G4 + tid] = (q0 + q1) + (q2 + q3);
                UNPACK2(q0, q1, e0); UNPACK2(q2, q3, e1);
                gsh[(2 * p + 1) * G4 + tid] = (q0 + q1) + (q2 + q3);
            }
        }

        // Stage inputs to smem
        if (layer > 0) {
            if (tid < nr * 25) {
                int r = tid / 25, p4 = tid - r * 25;
                *(float4*)&hprev[r * HH + p4 * 4] = v4;
            }
        } else {
            if (tid < nr * 5) hprev[tid] = xv;
        }
        __syncthreads();                       // S2

        // Delayed publish: h up to t-1 is now globally visible (fence@S1 + bar)
        if (tid == 0 && layer < 4 && t > 0) g_flag[layer][pb] = base + (unsigned)t;

        // Phase B: input projection dot
        if (tid < G4) {
            if (layer > 0) {
                const ulonglong2* wp = (const ulonglong2*)&Wihs[tid * HH];
                for (int p = 0; p < np; p++) {
                    const ulonglong2* hA = (const ulonglong2*)&hprev[(2 * p) * HH];
                    const ulonglong2* hB = (const ulonglong2*)&hprev[(2 * p + 1) * HH];
                    ull a0, a1, e0, e1;
                    PACK2(a0, 0.f, 0.f); PACK2(a1, 0.f, 0.f);
                    PACK2(e0, 0.f, 0.f); PACK2(e1, 0.f, 0.f);
#pragma unroll
                    for (int j = 0; j < 25; j++) {
                        ulonglong2 w = wp[j];
                        ulonglong2 pA = hA[j], pB = hB[j];
                        FMA2(a0, w.x, pA.x, a0);
                        FMA2(a1, w.y, pA.y, a1);
                        FMA2(e0, w.x, pB.x, e0);
                        FMA2(e1, w.y, pB.y, e1);
                    }
                    float q0, q1, q2, q3;
                    UNPACK2(q0, q1, a0); UNPACK2(q2, q3, a1);
                    gsh[(2 * p) * G4 + tid] += (q0 + q1) + (q2 + q3);
                    UNPACK2(q0, q1, e0); UNPACK2(q2, q3, e1);
                    gsh[(2 * p + 1) * G4 + tid] += (q0 + q1) + (q2 + q3);
                }
            } else {
#pragma unroll 4
                for (int r = 0; r < 16; r++) {
                    const float* xr = &hprev[r * 5];
                    float s = w0[0] * xr[0] + w0[1] * xr[1] + w0[2] * xr[2]
                            + w0[3] * xr[3] + w0[4] * xr[4];
                    gsh[r * G4 + tid] += s;
                }
            }
        }
        __syncthreads();                       // S3

        // Activation + state update + output store
#pragma unroll
        for (int q = 0; q < 4; q++) {
            int u = tid + q * 416;
            if (u < nr * HH) {
                int r = u / HH, n = u - r * HH;
                const float* gp = &gsh[r * G4 + n];
                float iv = sigf(gp[0]);
                float fv = sigf(gp[100]);
                float gv = tanh_(gp[200]);
                float ov = sigf(gp[300]);
                c[q] = fv * c[q] + iv * gv;
                float hv = ov * tanh_(c[q]);
                hown[r * HH + n] = hv;
                if (layer < 4)
                    g_h[(((size_t)layer * Bsz + row0 + r) * Tlen + t) * HH + n] = hv;
                else if (t == Tlen - 1)
                    g_hLast[(row0 + r) * HH + n] = hv;
            }
        }
        __syncthreads();                       // S4: hown ready for next step
    }

    // Final publish (t = T-1 data)
    if (layer < 4) {
        __threadfence();
        __syncthreads();
        if (tid == 0) g_flag[layer][pb] = base + (unsigned)Tlen;
    }
}

// ---------------------------------------------------------------------------
// BN (eval) + 3-layer MLP head on g_hLast. One block per batch row.
// ---------------------------------------------------------------------------
__global__ void head_kernel(const float* __restrict__ gamma,
                            const float* __restrict__ beta,
                            const float* __restrict__ rmean,
                            const float* __restrict__ rvar,
                            const float* __restrict__ W1, const float* __restrict__ b1,
                            const float* __restrict__ W2, const float* __restrict__ b2,
                            const float* __restrict__ W3, const float* __restrict__ b3,
                            float* __restrict__ out)
{
    __shared__ float xa[HH], ya[HH];
    int b = blockIdx.x, tid = threadIdx.x;

    if (tid < HH) {
        float v = g_hLast[b * HH + tid];
        xa[tid] = (v - rmean[tid]) * rsqrtf(rvar[tid] + 1e-5f) * gamma[tid] + beta[tid];
    }
    __syncthreads();
    if (tid < HH) {
        float a = b1[tid];
#pragma unroll 4
        for (int k = 0; k < HH; k++) a += xa[k] * W1[(size_t)tid * HH + k];
        ya[tid] = fmaxf(a, 0.0f);
    }
    __syncthreads();
    if (tid < HH) {
        float a = b2[tid];
#pragma unroll 4
        for (int k = 0; k < HH; k++) a += ya[k] * W2[(size_t)tid * HH + k];
        xa[tid] = fmaxf(a, 0.0f);
    }
    __syncthreads();
    if (tid < Oout) {
        float a = b3[tid];
#pragma unroll 4
        for (int k = 0; k < HH; k++) a += xa[k] * W3[(size_t)tid * HH + k];
        out[(size_t)b * Oout + tid] = a;
    }
}

// ---------------------------------------------------------------------------
// kernel_launch
// ---------------------------------------------------------------------------
extern "C" void kernel_launch(void* const* d_in, const int* in_sizes, int n_in,
                              void* d_out, int out_size)
{
    const float* x     = (const float*)d_in[0];
    const float* W_ih0 = (const float*)d_in[1];
    const float* W_hh0 = (const float*)d_in[2];
    const float* b0    = (const float*)d_in[3];
    const float* W_ih  = (const float*)d_in[4];
    const float* W_hh  = (const float*)d_in[5];
    const float* bb    = (const float*)d_in[6];
    const float* gamma = (const float*)d_in[7];
    const float* beta  = (const float*)d_in[8];
    const float* rmean = (const float*)d_in[9];
    const float* rvar  = (const float*)d_in[10];
    const float* W1    = (const float*)d_in[11];
    const float* b1    = (const float*)d_in[12];
    const float* W2    = (const float*)d_in[13];
    const float* b2    = (const float*)d_in[14];
    const float* W3    = (const float*)d_in[15];
    const float* b3    = (const float*)d_in[16];
    float* out = (float*)d_out;

    static int smem_set = 0;
    if (!smem_set) {
        cudaFuncSetAttribute((const void*)lstm_wave,
                             cudaFuncAttributeMaxDynamicSharedMemorySize, SMEM_BYTES);
        smem_set = 1;
    }

    // All 5 layers in one persistent wavefront grid (144 blocks <= 148 SMs).
    lstm_wave<<<144, 416, SMEM_BYTES>>>(x, W_ih0, W_hh0, b0, W_ih, W_hh, bb);

    head_kernel<<<Bsz, 128>>>(gamma, beta, rmean, rvar,
                              W1, b1, W2, b2, W3, b3, out);
}